// round 1
// baseline (speedup 1.0000x reference)
#include <cuda_runtime.h>
#include <math.h>

// Problem constants
#define V_SIZE 50257
#define E_DIM 512
#define BL 16384          // B*L = 8*2048
#define NR 100
#define NPAD 128
#define NORM_TERM 10.82490511970208f   // ln(50257)
#define LOG_NR 4.605170185988092f      // ln(100)

// Scratch (device globals; no cudaMalloc allowed)
__device__ float g_bT[E_DIM * NPAD];   // noise emb, k-major, padded cols zeroed (256KB)
__device__ float g_c[NPAD];            // folded constants per noise slot
__device__ float g_x0[BL];             // target-slot logits x0 per row
__device__ float g_part[128];          // per-block partial loss sums

__device__ __forceinline__ float softplusf(float x) {
    // log(1+e^x) = max(x,0) + log1p(exp(-|x|))
    return fmaxf(x, 0.0f) + log1pf(expf(-fabsf(x)));
}

// ---------------------------------------------------------------------------
// Kernel 1: gather noise embeddings (k-major, padded) + fold constants
// ---------------------------------------------------------------------------
__global__ void prep_kernel(const float* __restrict__ emb,
                            const float* __restrict__ bias,
                            const float* __restrict__ lpn,
                            const int*   __restrict__ nidx) {
    __shared__ int sn[NPAD];
    int tid = threadIdx.x;
    if (tid < NPAD) sn[tid] = (tid < NR) ? nidx[tid] : 0;
    __syncthreads();

    if (blockIdx.x == 0 && tid < NPAD) {
        if (tid < NR) {
            int n = sn[tid];
            g_c[tid] = bias[n] - NORM_TERM - lpn[n] - LOG_NR;
        } else {
            g_c[tid] = -1e30f;   // softplus(-1e30) == 0 -> padded cols contribute nothing
        }
    }

    int total = E_DIM * NPAD;
    for (int idx = blockIdx.x * blockDim.x + tid; idx < total; idx += gridDim.x * blockDim.x) {
        int k = idx >> 7;        // / NPAD
        int j = idx & (NPAD - 1);
        g_bT[idx] = (j < NR) ? emb[(size_t)sn[j] * E_DIM + k] : 0.0f;
    }
}

// ---------------------------------------------------------------------------
// Kernel 2: target-slot logit per row: x0 = dot(in,emb[t]) + bias[t] - lnV - lpn[t] - ln100
// One warp per row. 2048 blocks x 256 threads = 16384 warps.
// ---------------------------------------------------------------------------
__global__ void __launch_bounds__(256) targ_kernel(const float* __restrict__ inp,
                                                   const float* __restrict__ emb,
                                                   const float* __restrict__ bias,
                                                   const float* __restrict__ lpn,
                                                   const int*   __restrict__ target) {
    int warp = (blockIdx.x * blockDim.x + threadIdx.x) >> 5;
    int lane = threadIdx.x & 31;
    if (warp >= BL) return;

    int t = target[warp];  // same address for all lanes -> broadcast
    const float4* ip = (const float4*)(inp + (size_t)warp * E_DIM);
    const float4* ep = (const float4*)(emb + (size_t)t * E_DIM);

    float dot = 0.0f;
#pragma unroll
    for (int s = 0; s < 4; s++) {
        float4 a = ip[lane + 32 * s];
        float4 b = ep[lane + 32 * s];
        dot += a.x * b.x + a.y * b.y + a.z * b.z + a.w * b.w;
    }
#pragma unroll
    for (int off = 16; off > 0; off >>= 1)
        dot += __shfl_down_sync(0xFFFFFFFFu, dot, off);

    if (lane == 0)
        g_x0[warp] = dot + bias[t] - NORM_TERM - lpn[t] - LOG_NR;
}

// ---------------------------------------------------------------------------
// Kernel 3: 128x128x512 register-tiled GEMM (M-tile per block) fused with
// softplus epilogue. Deterministic in-block reduction -> g_part[block].
// 128 blocks x 256 threads; each thread computes an 8x8 tile.
// ---------------------------------------------------------------------------
__global__ void __launch_bounds__(256) gemm_loss_kernel(const float* __restrict__ inp) {
    __shared__ float As[128][33];      // +1 pad: conflict-free scalar reads/stores
    __shared__ float Bs[32][NPAD];
    __shared__ float cs[NPAD];
    __shared__ float red[16 * 128];
    __shared__ float rowloss[128];

    int tid = threadIdx.x;
    int tx = tid & 15;                 // col group (8 cols each)
    int ty = tid >> 4;                 // row group (8 rows each)
    int row0 = blockIdx.x * 128;

    if (tid < NPAD) cs[tid] = g_c[tid];

    float acc[8][8];
#pragma unroll
    for (int i = 0; i < 8; i++)
#pragma unroll
        for (int j = 0; j < 8; j++) acc[i][j] = 0.0f;

    const int kq = tid & 7;            // A-load: float4 slot within k-chunk
    const int rg = tid >> 3;           // A-load: row group (32 rows/pass)
    const int j4 = tid & 31;           // B-load: float4 col slot
    const int kr = tid >> 5;           // B-load: k row (8/pass)

    for (int k0 = 0; k0 < E_DIM; k0 += 32) {
        __syncthreads();
        // Load A tile: 128 rows x 32 k
#pragma unroll
        for (int it = 0; it < 4; it++) {
            int r = rg + 32 * it;
            float4 v = *(const float4*)(inp + (size_t)(row0 + r) * E_DIM + k0 + kq * 4);
            As[r][kq * 4 + 0] = v.x;
            As[r][kq * 4 + 1] = v.y;
            As[r][kq * 4 + 2] = v.z;
            As[r][kq * 4 + 3] = v.w;
        }
        // Load B tile: 32 k x 128 cols (k-major in g_bT, coalesced)
#pragma unroll
        for (int it = 0; it < 4; it++) {
            int k = kr + 8 * it;
            *(float4*)&Bs[k][j4 * 4] = *(const float4*)&g_bT[(size_t)(k0 + k) * NPAD + j4 * 4];
        }
        __syncthreads();

#pragma unroll
        for (int k = 0; k < 32; k++) {
            float4 b0 = *(float4*)&Bs[k][tx * 8];
            float4 b1 = *(float4*)&Bs[k][tx * 8 + 4];
            float bb[8] = {b0.x, b0.y, b0.z, b0.w, b1.x, b1.y, b1.z, b1.w};
#pragma unroll
            for (int i = 0; i < 8; i++) {
                float a = As[ty * 8 + i][k];
#pragma unroll
                for (int j = 0; j < 8; j++) acc[i][j] += a * bb[j];
            }
        }
    }

    // Epilogue: per-row sum of softplus(dot + c_j); padded cols give exactly 0.
    float rl[8];
#pragma unroll
    for (int i = 0; i < 8; i++) {
        float s = 0.0f;
#pragma unroll
        for (int j = 0; j < 8; j++)
            s += softplusf(acc[i][j] + cs[tx * 8 + j]);
        rl[i] = s;
    }

    __syncthreads();
#pragma unroll
    for (int i = 0; i < 8; i++)
        red[tx * 128 + ty * 8 + i] = rl[i];
    __syncthreads();

    if (tid < 128) {
        int row = tid;
        float s = 0.0f;
#pragma unroll
        for (int t = 0; t < 16; t++) s += red[t * 128 + row];
        // target slot: softplus(x0) - x0  (label = 1)
        float x0 = g_x0[row0 + row];
        s += softplusf(x0) - x0;
        rowloss[row] = s;
    }
    __syncthreads();

    if (tid == 0) {
        float s = 0.0f;
        for (int r = 0; r < 128; r++) s += rowloss[r];   // fixed order -> deterministic
        g_part[blockIdx.x] = s;
    }
}

// ---------------------------------------------------------------------------
// Kernel 4: final deterministic tree reduce and mean
// ---------------------------------------------------------------------------
__global__ void finalize_kernel(float* __restrict__ out) {
    __shared__ float s[128];
    int tid = threadIdx.x;
    s[tid] = g_part[tid];
    __syncthreads();
#pragma unroll
    for (int off = 64; off > 0; off >>= 1) {
        if (tid < off) s[tid] += s[tid + off];
        __syncthreads();
    }
    if (tid == 0) out[0] = s[0] * (1.0f / (float)BL);
}

// ---------------------------------------------------------------------------
extern "C" void kernel_launch(void* const* d_in, const int* in_sizes, int n_in,
                              void* d_out, int out_size) {
    const float* inp  = (const float*)d_in[0];   // (B,L,E) f32
    const float* emb  = (const float*)d_in[1];   // (V,E)  f32
    const float* bias = (const float*)d_in[2];   // (V,)   f32
    const float* lpn  = (const float*)d_in[3];   // (V,)   f32
    const int*   tgt  = (const int*)  d_in[4];   // (B,L)  i32
    const int*   nidx = (const int*)  d_in[5];   // (NR,)  i32
    float* out = (float*)d_out;

    prep_kernel<<<128, 256>>>(emb, bias, lpn, nidx);
    targ_kernel<<<BL / 8, 256>>>(inp, emb, bias, lpn, tgt);
    gemm_loss_kernel<<<BL / 128, 256>>>(inp);
    finalize_kernel<<<1, 128>>>(out);
}

// round 3
// speedup vs baseline: 1.4497x; 1.4497x over previous
#include <cuda_runtime.h>
#include <cuda_bf16.h>
#include <math.h>
#include <stdint.h>

#define E_DIM 512
#define BLROWS 16384
#define NRR 100
#define NPAD 112                        // padded noise cols (14 n-tiles of 8)
#define NORM_TERM 10.82490511970208f    // ln(50257)
#define LOG_NR 4.605170185988092f       // ln(100)
#define ASTR 144                        // A smem row stride bytes (72 bf16)
#define ABUF 18432                      // 128*144 per A buffer
#define BSTR 1040                       // B smem row stride bytes (520 bf16)

__device__ float g_part[128];
__device__ int   g_ctr = 0;             // self-resetting (graph-replay safe)

__device__ __forceinline__ uint32_t smem_u32(const void* p) {
    uint32_t a;
    asm("{ .reg .u64 t; cvta.to.shared.u64 t, %1; cvt.u32.u64 %0, t; }" : "=r"(a) : "l"(p));
    return a;
}
__device__ __forceinline__ void ldmatrix_x4(uint32_t& r0, uint32_t& r1,
                                            uint32_t& r2, uint32_t& r3, uint32_t addr) {
    asm volatile("ldmatrix.sync.aligned.m8n8.x4.shared.b16 {%0,%1,%2,%3}, [%4];"
                 : "=r"(r0), "=r"(r1), "=r"(r2), "=r"(r3) : "r"(addr));
}
__device__ __forceinline__ void mma16816(float* d, const uint32_t* a,
                                         uint32_t b0, uint32_t b1) {
    asm volatile("mma.sync.aligned.m16n8k16.row.col.f32.bf16.bf16.f32 "
                 "{%0,%1,%2,%3}, {%4,%5,%6,%7}, {%8,%9}, {%0,%1,%2,%3};"
                 : "+f"(d[0]), "+f"(d[1]), "+f"(d[2]), "+f"(d[3])
                 : "r"(a[0]), "r"(a[1]), "r"(a[2]), "r"(a[3]), "r"(b0), "r"(b1));
}
__device__ __forceinline__ float softplus_exact(float x) {
    return fmaxf(x, 0.0f) + log1pf(expf(-fabsf(x)));
}
__device__ __forceinline__ uint2 cvt_bf16x4(float4 v) {
    __nv_bfloat162 p0 = __float22bfloat162_rn(make_float2(v.x, v.y));
    __nv_bfloat162 p1 = __float22bfloat162_rn(make_float2(v.z, v.w));
    uint2 r;
    r.x = *reinterpret_cast<uint32_t*>(&p0);
    r.y = *reinterpret_cast<uint32_t*>(&p1);
    return r;
}

// ---------------------------------------------------------------------------
// Single fused kernel: per-CTA 128x112x512 bf16 HMMA GEMM with
//  - B gathered from gmem (L2-broadcast across CTAs)
//  - A f32->bf16 double-buffered, software pipelined, fused exact target dot
//  - softplus epilogue on register accumulators (product trick)
//  - fused deterministic grid reduction (self-resetting counter)
// grid 128 x 256 threads. dynamic smem = 1K slack + 2*18432 (A) + 112*1040 (B)
// ---------------------------------------------------------------------------
__global__ void __launch_bounds__(256, 1)
mega_kernel(const float* __restrict__ inp,
            const float* __restrict__ emb,
            const float* __restrict__ bias,
            const float* __restrict__ lpn,
            const int*   __restrict__ tgt,
            const int*   __restrict__ nidx,
            float* __restrict__ out) {
    extern __shared__ char dsm[];
    __shared__ float cs[NPAD];
    __shared__ int   s_n[NPAD];
    __shared__ int   s_t[128];
    __shared__ float s_xc[128];
    __shared__ float s_tdot[128];
    __shared__ float s_red[128];

    const int tid = threadIdx.x;
    const int row0 = blockIdx.x * 128;

    const uint32_t db = smem_u32(dsm);
    const uint32_t abase = (db + 1023u) & ~1023u;
    const uint32_t bbase = abase + 2 * ABUF;
    char* ap = dsm + (abase - db);
    char* bp = ap + 2 * ABUF;

    if (tid < NPAD) {
        int nv = (tid < NRR) ? nidx[tid] : -1;
        s_n[tid] = nv;
        cs[tid] = (tid < NRR) ? (bias[nv] - NORM_TERM - lpn[nv] - LOG_NR) : -1e30f;
    }
    if (tid < 128) {
        int t = tgt[row0 + tid];
        s_t[tid] = t;
        s_xc[tid] = bias[t] - NORM_TERM - lpn[t] - LOG_NR;
    }
    __syncthreads();

    // --- B fill: gather noise embeddings -> bf16 [n][k], padded rows zero ---
    for (int idx = tid; idx < NPAD * 128; idx += 256) {
        int n = idx >> 7;          // 0..111
        int q = idx & 127;         // float4 index along k
        int t = s_n[n];
        float4 v = make_float4(0.f, 0.f, 0.f, 0.f);
        if (t >= 0) v = *(const float4*)(emb + (size_t)t * E_DIM + q * 4);
        *(uint2*)(bp + n * BSTR + q * 8) = cvt_bf16x4(v);
    }

    // --- A loader setup: 16 threads per row, 8 rows per thread ---
    const int l4 = tid & 15;
    const int rg = tid >> 4;
    const float* ipt = inp + (size_t)(row0 + rg) * E_DIM + l4 * 4;
    const float* ept[8];
#pragma unroll
    for (int i = 0; i < 8; i++)
        ept[i] = emb + (size_t)s_t[rg + 16 * i] * E_DIM + l4 * 4;
    char* asts = ap + rg * ASTR + l4 * 8;

    float tacc[8];
#pragma unroll
    for (int i = 0; i < 8; i++) tacc[i] = 0.f;

    float4 va[8], ve[8];
    // LDG + STS chunk 0 into buffer 0
#pragma unroll
    for (int i = 0; i < 8; i++) {
        va[i] = *(const float4*)(ipt + i * 8192);
        ve[i] = *(const float4*)(ept[i]);
    }
#pragma unroll
    for (int i = 0; i < 8; i++) {
        tacc[i] += va[i].x * ve[i].x + va[i].y * ve[i].y + va[i].z * ve[i].z + va[i].w * ve[i].w;
        *(uint2*)(asts + i * (16 * ASTR)) = cvt_bf16x4(va[i]);
    }
    __syncthreads();

    // --- MMA setup ---
    const int lane = tid & 31;
    const int warp = tid >> 5;
    const int m0 = warp * 16;
    const uint32_t a_off = abase + (uint32_t)(m0 + (lane & 15)) * ASTR + ((lane >> 4) << 4);
    const uint32_t b_off = bbase + (uint32_t)((lane & 7) + ((lane >> 4) << 3)) * BSTR
                                 + (((lane >> 3) & 1) << 4);

    float acc[14][4];
#pragma unroll
    for (int n = 0; n < 14; n++)
#pragma unroll
        for (int j = 0; j < 4; j++) acc[n][j] = 0.f;

    // --- Main pipelined loop over 8 K-chunks of 64 ---
    for (int c = 0; c < 8; c++) {
        if (c < 7) {
#pragma unroll
            for (int i = 0; i < 8; i++) {
                va[i] = *(const float4*)(ipt + (c + 1) * 64 + i * 8192);
                ve[i] = *(const float4*)(ept[i] + (c + 1) * 64);
            }
        }
        // MMA on buffer c&1
        {
            const uint32_t ab = a_off + (uint32_t)(c & 1) * ABUF;
            const uint32_t bb = b_off + (uint32_t)c * 128;   // c*64 k * 2B
#pragma unroll
            for (int k0 = 0; k0 < 4; k0++) {
                uint32_t a[4];
                ldmatrix_x4(a[0], a[1], a[2], a[3], ab + k0 * 32);
#pragma unroll
                for (int nt = 0; nt < 7; nt++) {
                    uint32_t b0, b1, b2, b3;
                    ldmatrix_x4(b0, b1, b2, b3, bb + nt * (16 * BSTR) + k0 * 32);
                    mma16816(acc[nt * 2], a, b0, b1);
                    mma16816(acc[nt * 2 + 1], a, b2, b3);
                }
            }
        }
        if (c < 7) {
            char* dst = ap + ((c + 1) & 1) * ABUF + (rg * ASTR + l4 * 8);
#pragma unroll
            for (int i = 0; i < 8; i++) {
                tacc[i] += va[i].x * ve[i].x + va[i].y * ve[i].y + va[i].z * ve[i].z + va[i].w * ve[i].w;
                *(uint2*)(dst + i * (16 * ASTR)) = cvt_bf16x4(va[i]);
            }
        }
        __syncthreads();
    }

    // --- finish exact target dots ---
#pragma unroll
    for (int i = 0; i < 8; i++) {
        float v = tacc[i];
        v += __shfl_xor_sync(0xFFFFFFFFu, v, 8);
        v += __shfl_xor_sync(0xFFFFFFFFu, v, 4);
        v += __shfl_xor_sync(0xFFFFFFFFu, v, 2);
        v += __shfl_xor_sync(0xFFFFFFFFu, v, 1);
        if (l4 == 0) s_tdot[rg + 16 * i] = v;
    }
    __syncthreads();

    // --- softplus epilogue on register accumulators ---
    {
        const int g = lane >> 2;
        const int tq = lane & 3;
        float plo = 1.f, phi = 1.f;      // product trick: x <= -1.8 always
#pragma unroll
        for (int nt = 0; nt < 14; nt++) {
            float c0 = cs[nt * 8 + 2 * tq];
            float c1 = cs[nt * 8 + 2 * tq + 1];
            plo *= (1.f + __expf(acc[nt][0] + c0));
            plo *= (1.f + __expf(acc[nt][1] + c1));
            phi *= (1.f + __expf(acc[nt][2] + c0));
            phi *= (1.f + __expf(acc[nt][3] + c1));
        }
        float slo = __logf(plo);
        float shi = __logf(phi);
        slo += __shfl_xor_sync(0xFFFFFFFFu, slo, 1);
        slo += __shfl_xor_sync(0xFFFFFFFFu, slo, 2);
        shi += __shfl_xor_sync(0xFFFFFFFFu, shi, 1);
        shi += __shfl_xor_sync(0xFFFFFFFFu, shi, 2);
        if (tq == 0) {
            int rlo = m0 + g, rhi = rlo + 8;
            float x0 = s_tdot[rlo] + s_xc[rlo];
            s_red[rlo] = slo + softplus_exact(x0) - x0;   // target slot, label=1
            x0 = s_tdot[rhi] + s_xc[rhi];
            s_red[rhi] = shi + softplus_exact(x0) - x0;
        }
    }
    __syncthreads();

    // --- fixed-order block reduction + fused grid finalize ---
    if (tid < 32) {
        float s = s_red[tid] + s_red[tid + 32] + s_red[tid + 64] + s_red[tid + 96];
        s += __shfl_xor_sync(0xFFFFFFFFu, s, 16);
        s += __shfl_xor_sync(0xFFFFFFFFu, s, 8);
        s += __shfl_xor_sync(0xFFFFFFFFu, s, 4);
        s += __shfl_xor_sync(0xFFFFFFFFu, s, 2);
        s += __shfl_xor_sync(0xFFFFFFFFu, s, 1);
        if (tid == 0) {
            g_part[blockIdx.x] = s;
            __threadfence();
            int old = atomicAdd(&g_ctr, 1);
            if (old == 127) {            // last block finalizes
                __threadfence();
                float tot = 0.f;
#pragma unroll 1
                for (int r = 0; r < 128; r++)
                    tot += *((volatile float*)&g_part[r]);
                out[0] = tot * (1.0f / (float)BLROWS);
                g_ctr = 0;               // reset for graph replay
            }
        }
    }
}

// ---------------------------------------------------------------------------
extern "C" void kernel_launch(void* const* d_in, const int* in_sizes, int n_in,
                              void* d_out, int out_size) {
    const float* inp  = (const float*)d_in[0];
    const float* emb  = (const float*)d_in[1];
    const float* bias = (const float*)d_in[2];
    const float* lpn  = (const float*)d_in[3];
    const int*   tgt  = (const int*)  d_in[4];
    const int*   nidx = (const int*)  d_in[5];
    float* out = (float*)d_out;

    const int DSM = 1024 + 2 * ABUF + NPAD * BSTR;   // 154368 B
    cudaFuncSetAttribute(mega_kernel, cudaFuncAttributeMaxDynamicSharedMemorySize, DSM);
    mega_kernel<<<128, 256, DSM>>>(inp, emb, bias, lpn, tgt, nidx, out);
}

// round 4
// speedup vs baseline: 1.6459x; 1.1353x over previous
#include <cuda_runtime.h>
#include <cuda_bf16.h>
#include <math.h>
#include <stdint.h>

#define E_DIM 512
#define BLROWS 16384
#define NRR 100
#define NPAD 112                        // 14 n-tiles of 8
#define NORM_TERM 10.82490511970208f    // ln(50257)
#define LOG_NR 4.605170185988092f       // ln(100)
#define ASTR 144                        // A smem row stride bytes (72 bf16)
#define ABUF 18432                      // 128*144 per A stage
#define BSTR 1040                       // B smem row stride bytes (520 bf16)

__device__ float g_part[128];
__device__ int   g_ctr = 0;             // self-resetting (graph-replay safe)

__device__ __forceinline__ uint32_t smem_u32(const void* p) {
    uint32_t a;
    asm("{ .reg .u64 t; cvta.to.shared.u64 t, %1; cvt.u32.u64 %0, t; }" : "=r"(a) : "l"(p));
    return a;
}
__device__ __forceinline__ void ldmatrix_x4(uint32_t& r0, uint32_t& r1,
                                            uint32_t& r2, uint32_t& r3, uint32_t addr) {
    asm volatile("ldmatrix.sync.aligned.m8n8.x4.shared.b16 {%0,%1,%2,%3}, [%4];"
                 : "=r"(r0), "=r"(r1), "=r"(r2), "=r"(r3) : "r"(addr));
}
__device__ __forceinline__ void ldmatrix_x2(uint32_t& r0, uint32_t& r1, uint32_t addr) {
    asm volatile("ldmatrix.sync.aligned.m8n8.x2.shared.b16 {%0,%1}, [%2];"
                 : "=r"(r0), "=r"(r1) : "r"(addr));
}
__device__ __forceinline__ void mma16816(float* d, const uint32_t* a,
                                         uint32_t b0, uint32_t b1) {
    asm volatile("mma.sync.aligned.m16n8k16.row.col.f32.bf16.bf16.f32 "
                 "{%0,%1,%2,%3}, {%4,%5,%6,%7}, {%8,%9}, {%0,%1,%2,%3};"
                 : "+f"(d[0]), "+f"(d[1]), "+f"(d[2]), "+f"(d[3])
                 : "r"(a[0]), "r"(a[1]), "r"(a[2]), "r"(a[3]), "r"(b0), "r"(b1));
}
__device__ __forceinline__ float softplus_exact(float x) {
    return fmaxf(x, 0.0f) + log1pf(expf(-fabsf(x)));
}
__device__ __forceinline__ uint2 cvt_bf16x4(float4 v) {
    __nv_bfloat162 p0 = __float22bfloat162_rn(make_float2(v.x, v.y));
    __nv_bfloat162 p1 = __float22bfloat162_rn(make_float2(v.z, v.w));
    uint2 r;
    r.x = *reinterpret_cast<uint32_t*>(&p0);
    r.y = *reinterpret_cast<uint32_t*>(&p1);
    return r;
}

// ---------------------------------------------------------------------------
// 512 threads / 16 warps per CTA. Warp w: M-slab (w&7)*16, N-group w>>3 (7 tiles).
// 3-stage A pipeline (f32->bf16 convert + fused exact target dot in the loader),
// B resident for full K, softplus epilogue on register accs, fused grid reduce.
// ---------------------------------------------------------------------------
__global__ void __launch_bounds__(512, 1)
mega_kernel(const float* __restrict__ inp,
            const float* __restrict__ emb,
            const float* __restrict__ bias,
            const float* __restrict__ lpn,
            const int*   __restrict__ tgt,
            const int*   __restrict__ nidx,
            float* __restrict__ out) {
    extern __shared__ char dsm[];
    __shared__ float cs[NPAD];
    __shared__ int   s_n[NPAD];
    __shared__ int   s_t[128];
    __shared__ float s_xc[128];
    __shared__ float s_tdot[128];
    __shared__ float s_red[2][128];
    __shared__ float s_fin[128];

    const int tid = threadIdx.x;
    const int row0 = blockIdx.x * 128;

    const uint32_t db = smem_u32(dsm);
    const uint32_t abase = (db + 1023u) & ~1023u;
    const uint32_t bbase = abase + 3 * ABUF;
    char* ap = dsm + (abase - db);
    char* bp = ap + 3 * ABUF;

    if (tid < NPAD) {
        int nv = (tid < NRR) ? nidx[tid] : -1;
        s_n[tid] = nv;
        cs[tid] = (tid < NRR) ? (bias[nv] - NORM_TERM - lpn[nv] - LOG_NR) : -1e30f;
    }
    if (tid >= 128 && tid < 256) {
        int r = tid - 128;
        int t = tgt[row0 + r];
        s_t[r] = t;
        s_xc[r] = bias[t] - NORM_TERM - lpn[t] - LOG_NR;
    }
    __syncthreads();

    // --- B fill: gather noise embeddings -> bf16 [n][k], padded rows zero ---
    for (int idx = tid; idx < NPAD * 128; idx += 512) {
        int n = idx >> 7;
        int q = idx & 127;
        int t = s_n[n];
        float4 v = make_float4(0.f, 0.f, 0.f, 0.f);
        if (t >= 0) v = *(const float4*)(emb + (size_t)t * E_DIM + q * 4);
        *(uint2*)(bp + n * BSTR + q * 8) = cvt_bf16x4(v);
    }

    // --- A loader: 16 threads per row, 4 rows per thread (rg, rg+32, ...) ---
    const int l4 = tid & 15;
    const int rg = tid >> 4;           // 0..31
    const float* ipt = inp + (size_t)(row0 + rg) * E_DIM + l4 * 4;
    const float* ept[4];
#pragma unroll
    for (int i = 0; i < 4; i++)
        ept[i] = emb + (size_t)s_t[rg + 32 * i] * E_DIM + l4 * 4;
    const uint32_t asts = rg * ASTR + l4 * 8;

    float tacc[4];
#pragma unroll
    for (int i = 0; i < 4; i++) tacc[i] = 0.f;

    // Prologue: chunks 0 and 1 -> stages 0, 1
#pragma unroll
    for (int c = 0; c < 2; c++) {
        float4 va[4], ve[4];
#pragma unroll
        for (int i = 0; i < 4; i++) {
            va[i] = *(const float4*)(ipt + c * 64 + i * 16384);
            ve[i] = *(const float4*)(ept[i] + c * 64);
        }
        char* dst = ap + c * ABUF + asts;
#pragma unroll
        for (int i = 0; i < 4; i++) {
            tacc[i] += va[i].x * ve[i].x + va[i].y * ve[i].y + va[i].z * ve[i].z + va[i].w * ve[i].w;
            *(uint2*)(dst + i * (32 * ASTR)) = cvt_bf16x4(va[i]);
        }
    }
    __syncthreads();

    // --- MMA setup ---
    const int lane = tid & 31;
    const int warp = tid >> 5;
    const int m0 = (warp & 7) * 16;
    const int ngrp = warp >> 3;        // 0 or 1: n-tiles [7g, 7g+7)
    const uint32_t a_woff = (uint32_t)(m0 + (lane & 15)) * ASTR + ((lane >> 4) << 4);
    const uint32_t b_off = bbase + (uint32_t)(ngrp * 56 + (lane & 7) + ((lane >> 4) << 3)) * BSTR
                                 + (((lane >> 3) & 1) << 4);
    const uint32_t b2_off = bbase + (uint32_t)(ngrp * 56 + 48 + (lane & 7)) * BSTR
                                  + (((lane >> 3) & 1) << 4);

    float acc[7][4];
#pragma unroll
    for (int n = 0; n < 7; n++)
#pragma unroll
        for (int j = 0; j < 4; j++) acc[n][j] = 0.f;

    int bufm = 0, bufs = 2;            // MMA stage (c%3), store stage ((c+2)%3)

    for (int c = 0; c < 8; c++) {
        float4 va[4], ve[4];
        if (c < 6) {
#pragma unroll
            for (int i = 0; i < 4; i++) {
                va[i] = *(const float4*)(ipt + (c + 2) * 64 + i * 16384);
                ve[i] = *(const float4*)(ept[i] + (c + 2) * 64);
            }
        }
        // MMA chunk c from stage bufm
        {
            const uint32_t ab = abase + (uint32_t)bufm * ABUF + a_woff;
            const uint32_t bb = b_off + (uint32_t)c * 128;
            const uint32_t bb2 = b2_off + (uint32_t)c * 128;
#pragma unroll
            for (int k0 = 0; k0 < 4; k0++) {
                uint32_t a[4];
                ldmatrix_x4(a[0], a[1], a[2], a[3], ab + k0 * 32);
#pragma unroll
                for (int p = 0; p < 3; p++) {
                    uint32_t b0, b1, b2, b3;
                    ldmatrix_x4(b0, b1, b2, b3, bb + p * (16 * BSTR) + k0 * 32);
                    mma16816(acc[p * 2], a, b0, b1);
                    mma16816(acc[p * 2 + 1], a, b2, b3);
                }
                uint32_t b0, b1;
                ldmatrix_x2(b0, b1, bb2 + k0 * 32);
                mma16816(acc[6], a, b0, b1);
            }
        }
        if (c < 6) {
            char* dst = ap + bufs * ABUF + asts;
#pragma unroll
            for (int i = 0; i < 4; i++) {
                tacc[i] += va[i].x * ve[i].x + va[i].y * ve[i].y + va[i].z * ve[i].z + va[i].w * ve[i].w;
                *(uint2*)(dst + i * (32 * ASTR)) = cvt_bf16x4(va[i]);
            }
        }
        __syncthreads();
        bufm = (bufm == 2) ? 0 : bufm + 1;
        bufs = (bufs == 2) ? 0 : bufs + 1;
    }

    // --- finish exact target dots (reduce over 16 lanes sharing a row) ---
#pragma unroll
    for (int i = 0; i < 4; i++) {
        float v = tacc[i];
        v += __shfl_xor_sync(0xFFFFFFFFu, v, 8);
        v += __shfl_xor_sync(0xFFFFFFFFu, v, 4);
        v += __shfl_xor_sync(0xFFFFFFFFu, v, 2);
        v += __shfl_xor_sync(0xFFFFFFFFu, v, 1);
        if (l4 == 0) s_tdot[rg + 32 * i] = v;
    }

    // --- softplus epilogue (product trick; x <= -1.8 always) ---
    {
        const int g = lane >> 2;
        const int tq = lane & 3;
        float plo = 1.f, phi = 1.f;
#pragma unroll
        for (int nt = 0; nt < 7; nt++) {
            float c0 = cs[(ngrp * 7 + nt) * 8 + 2 * tq];
            float c1 = cs[(ngrp * 7 + nt) * 8 + 2 * tq + 1];
            plo *= (1.f + __expf(acc[nt][0] + c0));
            plo *= (1.f + __expf(acc[nt][1] + c1));
            phi *= (1.f + __expf(acc[nt][2] + c0));
            phi *= (1.f + __expf(acc[nt][3] + c1));
        }
        float slo = __logf(plo);
        float shi = __logf(phi);
        slo += __shfl_xor_sync(0xFFFFFFFFu, slo, 1);
        slo += __shfl_xor_sync(0xFFFFFFFFu, slo, 2);
        shi += __shfl_xor_sync(0xFFFFFFFFu, shi, 1);
        shi += __shfl_xor_sync(0xFFFFFFFFu, shi, 2);
        if (tq == 0) {
            s_red[ngrp][m0 + g] = slo;
            s_red[ngrp][m0 + g + 8] = shi;
        }
    }
    __syncthreads();

    // --- per-row combine (+ target slot), then fixed-order block reduction ---
    if (tid < 128) {
        float x0 = s_tdot[tid] + s_xc[tid];
        s_fin[tid] = s_red[0][tid] + s_red[1][tid] + softplus_exact(x0) - x0;
    }
    __syncthreads();
    if (tid < 32) {
        float s = s_fin[tid] + s_fin[tid + 32] + s_fin[tid + 64] + s_fin[tid + 96];
        s += __shfl_xor_sync(0xFFFFFFFFu, s, 16);
        s += __shfl_xor_sync(0xFFFFFFFFu, s, 8);
        s += __shfl_xor_sync(0xFFFFFFFFu, s, 4);
        s += __shfl_xor_sync(0xFFFFFFFFu, s, 2);
        s += __shfl_xor_sync(0xFFFFFFFFu, s, 1);
        if (tid == 0) {
            g_part[blockIdx.x] = s;
            __threadfence();
            int old = atomicAdd(&g_ctr, 1);
            if (old == 127) {
                __threadfence();
                float tot = 0.f;
#pragma unroll 1
                for (int r = 0; r < 128; r++)
                    tot += *((volatile float*)&g_part[r]);
                out[0] = tot * (1.0f / (float)BLROWS);
                g_ctr = 0;
            }
        }
    }
}

// ---------------------------------------------------------------------------
extern "C" void kernel_launch(void* const* d_in, const int* in_sizes, int n_in,
                              void* d_out, int out_size) {
    const float* inp  = (const float*)d_in[0];
    const float* emb  = (const float*)d_in[1];
    const float* bias = (const float*)d_in[2];
    const float* lpn  = (const float*)d_in[3];
    const int*   tgt  = (const int*)  d_in[4];
    const int*   nidx = (const int*)  d_in[5];
    float* out = (float*)d_out;

    const int DSM = 1024 + 3 * ABUF + NPAD * BSTR;   // ~172 KB
    cudaFuncSetAttribute(mega_kernel, cudaFuncAttributeMaxDynamicSharedMemorySize, DSM);
    mega_kernel<<<128, 512, DSM>>>(inp, emb, bias, lpn, tgt, nidx, out);
}